// round 2
// baseline (speedup 1.0000x reference)
#include <cuda_runtime.h>
#include <math.h>

#define B_   128
#define L_   64
#define D_   256
#define H_   512
#define AS_  512
#define AP_  256
#define G3H_ 1536
#define NEGV (-1.0e9f)

// ---------------- scratch (device globals; no allocation allowed) ----------------
__device__ float g_dense   [B_*L_*D_];     // dense_inputs [B,L,D]
__device__ float g_enc_gi  [B_*L_*G3H_];   // x@enc_Wi.T for all (b,t)
__device__ float g_decx_gi [B_*L_*G3H_];   // dense_inputs@dec_Wi[:,H:].T for all (b,l)
__device__ float g_enc_out [B_*L_*H_];     // masked encoder states
__device__ float g_enc_keys[B_*L_*AS_];
__device__ float g_ptr_keys[B_*L_*AP_];
__device__ float g_h   [B_*H_];
__device__ float g_gh  [B_*G3H_];
__device__ float g_gic [B_*G3H_];
__device__ float g_ctx [B_*H_];
__device__ float g_q   [B_*AS_];
__device__ float g_dout[B_*D_];
__device__ float g_pq  [B_*AP_];
__device__ int   g_idx [L_*B_];            // decoder input index per (t,b)
__device__ int   g_fo  [B_*L_];            // first occurrence of l in targets[b,:]

// ---------------- generic tiled SGEMM ----------------
// C[M,N] = A[M,K] * B  (+bias per column)
// WT=true : B(k,n) = Bm[n*ldb + k]   (PyTorch weight [N,K], y = x @ W.T)
// WT=false: B(k,n) = Bm[k*ldb + n]   (plain [K,N])
template<int BM,int BN,int TM,int TN,bool WT>
__device__ __forceinline__ void gemm_body(
    const float* __restrict__ A, int lda,
    const float* __restrict__ Bm, int ldb,
    const float* __restrict__ bias,
    float* __restrict__ C, int ldc, int K)
{
    constexpr int BKK = 16;
    constexpr int NT  = (BM/TM)*(BN/TN);
    __shared__ float As[BKK][BM];
    __shared__ float Bs[BKK][BN];
    const int tid = threadIdx.x;
    const int m0 = blockIdx.y*BM, n0 = blockIdx.x*BN;
    const int tc = tid % (BN/TN), tr = tid / (BN/TN);
    float acc[TM][TN];
#pragma unroll
    for (int i=0;i<TM;i++)
#pragma unroll
        for (int j=0;j<TN;j++) acc[i][j]=0.f;

    for (int k0=0;k0<K;k0+=BKK) {
        for (int i=tid;i<BM*BKK;i+=NT) {
            int r=i/BKK, kk=i%BKK;
            As[kk][r] = A[(m0+r)*lda + k0+kk];
        }
        if (WT) {
            for (int i=tid;i<BN*BKK;i+=NT) {
                int n=i/BKK, kk=i%BKK;
                Bs[kk][n] = Bm[(n0+n)*ldb + k0+kk];
            }
        } else {
            for (int i=tid;i<BN*BKK;i+=NT) {
                int kk=i/BN, n=i%BN;
                Bs[kk][n] = Bm[(k0+kk)*ldb + n0+n];
            }
        }
        __syncthreads();
#pragma unroll
        for (int kk=0;kk<BKK;kk++) {
            float a[TM], bb[TN];
#pragma unroll
            for (int i=0;i<TM;i++) a[i]=As[kk][tr*TM+i];
#pragma unroll
            for (int j=0;j<TN;j++) bb[j]=Bs[kk][tc*TN+j];
#pragma unroll
            for (int i=0;i<TM;i++)
#pragma unroll
                for (int j=0;j<TN;j++) acc[i][j] += a[i]*bb[j];
        }
        __syncthreads();
    }
#pragma unroll
    for (int i=0;i<TM;i++) {
        int m = m0 + tr*TM + i;
#pragma unroll
        for (int j=0;j<TN;j++) {
            int n = n0 + tc*TN + j;
            C[m*ldc+n] = acc[i][j] + (bias ? bias[n] : 0.f);
        }
    }
}

template<int BM,int BN,int TM,int TN,bool WT>
__global__ void __launch_bounds__(256) sgemm_k(
    const float* __restrict__ A, int lda,
    const float* __restrict__ Bm, int ldb,
    const float* __restrict__ bias,
    float* __restrict__ C, int ldc, int K)
{
    gemm_body<BM,BN,TM,TN,WT>(A,lda,Bm,ldb,bias,C,ldc,K);
}

// Decoder gate GEMMs fused via blockIdx.z: z=0 -> gh = h@dec_Wh.T, z=1 -> gic = ctx@dec_Wi[:, :H].T
__global__ void __launch_bounds__(256) dec_gates_k(
    const float* __restrict__ dec_Wh, const float* __restrict__ dec_Wi)
{
    if (blockIdx.z == 0)
        gemm_body<32,64,2,4,true>(g_h,  H_, dec_Wh, H_,  nullptr, g_gh,  G3H_, H_);
    else
        gemm_body<32,64,2,4,true>(g_ctx,H_, dec_Wi, 768, nullptr, g_gic, G3H_, H_);
}

// ---------------- small kernels ----------------
__global__ void zero_h_k() {
    int i = blockIdx.x*256 + threadIdx.x;
    g_h[i] = 0.f;
}

__global__ void dense_in_k(const float* __restrict__ in,
                           const float* __restrict__ W_in,
                           const float* __restrict__ b_in)
{
    int i = blockIdx.x*256 + threadIdx.x;     // B*L*D
    int m = i / D_, d = i % D_;
    g_dense[i] = in[m*2]*W_in[d*2] + in[m*2+1]*W_in[d*2+1] + b_in[d];
}

__global__ void masks_k(const int* __restrict__ targets) {
    int b = blockIdx.x, l = threadIdx.x;      // 64 threads
    int fo = L_;
    for (int s=0;s<L_;s++) if (targets[b*L_+s]==l) { fo = s; break; }
    g_fo[b*L_+l] = fo;
    g_idx[l*B_+b] = (l==0) ? 0 : targets[b*L_+l-1];
}

__device__ __forceinline__ float sigmf(float x){ return 1.f/(1.f+expf(-x)); }

__global__ void enc_pointwise_k(const float* __restrict__ bi,
                                const float* __restrict__ bh,
                                const int* __restrict__ lengths, int t)
{
    int i = blockIdx.x*256 + threadIdx.x;     // B*H
    int b = i >> 9, j = i & (H_-1);
    const float* gi = &g_enc_gi[(b*L_+t)*G3H_];
    const float* gh = &g_gh[b*G3H_];
    float ir = gi[j]        + bi[j];
    float iz = gi[j+H_]     + bi[j+H_];
    float in_= gi[j+2*H_]   + bi[j+2*H_];
    float hr = gh[j]        + bh[j];
    float hz = gh[j+H_]     + bh[j+H_];
    float hn = gh[j+2*H_]   + bh[j+2*H_];
    float r = sigmf(ir+hr);
    float z = sigmf(iz+hz);
    float n = tanhf(in_ + r*hn);
    float h = g_h[i];
    float hnew = (1.f-z)*n + z*h;
    g_h[i] = hnew;
    g_enc_out[(b*L_+t)*H_+j] = (t < lengths[b]) ? hnew : 0.f;
}

__global__ void hidden0_k(const int* __restrict__ lengths) {
    int i = blockIdx.x*256 + threadIdx.x;     // B*H
    int b = i >> 9, j = i & (H_-1);
    g_h[i] = g_enc_out[(b*L_ + lengths[b]-1)*H_ + j];
}

__global__ void attn_s2s_k(const float* __restrict__ v,
                           const int* __restrict__ lengths, int t)
{
    int b = blockIdx.x;
    __shared__ float sc[L_];
    int tid = threadIdx.x, lane = tid & 31, w = tid >> 5;
    int len = lengths[b];
    bool tvalid = (t < len);
    const float* qp = &g_q[b*AS_];
    for (int l = w; l < L_; l += 8) {
        const float* kp = &g_enc_keys[(b*L_+l)*AS_];
        float acc = 0.f;
#pragma unroll 4
        for (int a = lane; a < AS_; a += 32)
            acc += tanhf(qp[a] + kp[a]) * v[a];
        for (int o=16;o;o>>=1) acc += __shfl_down_sync(0xffffffffu, acc, o);
        if (lane==0) sc[l] = (tvalid && l < len) ? acc : NEGV;
    }
    __syncthreads();
    if (w == 0) {
        float v0 = sc[lane], v1 = sc[lane+32];
        float m = fmaxf(v0, v1);
        for (int o=16;o;o>>=1) m = fmaxf(m, __shfl_xor_sync(0xffffffffu, m, o));
        float e0 = expf(v0-m), e1 = expf(v1-m);
        float s = e0+e1;
        for (int o=16;o;o>>=1) s += __shfl_xor_sync(0xffffffffu, s, o);
        sc[lane] = e0/s; sc[lane+32] = e1/s;
    }
    __syncthreads();
    for (int j = tid; j < H_; j += 256) {
        float c = 0.f;
#pragma unroll 8
        for (int l=0;l<L_;l++) c += sc[l] * g_enc_out[(b*L_+l)*H_+j];
        g_ctx[b*H_+j] = c;
    }
}

__global__ void dec_pointwise_k(const float* __restrict__ bi,
                                const float* __restrict__ bh, int t)
{
    int i = blockIdx.x*256 + threadIdx.x;     // B*H
    int b = i >> 9, j = i & (H_-1);
    int idx = g_idx[t*B_+b];
    const float* gx = &g_decx_gi[(b*L_+idx)*G3H_];
    const float* gc = &g_gic[b*G3H_];
    const float* gh = &g_gh[b*G3H_];
    float ir = gx[j]      + gc[j]      + bi[j];
    float iz = gx[j+H_]   + gc[j+H_]   + bi[j+H_];
    float in_= gx[j+2*H_] + gc[j+2*H_] + bi[j+2*H_];
    float hr = gh[j]      + bh[j];
    float hz = gh[j+H_]   + bh[j+H_];
    float hn = gh[j+2*H_] + bh[j+2*H_];
    float r = sigmf(ir+hr);
    float z = sigmf(iz+hz);
    float n = tanhf(in_ + r*hn);
    float h = g_h[i];
    g_h[i] = (1.f-z)*n + z*h;
}

__global__ void ptr_attn_k(const float* __restrict__ pv,
                           const int* __restrict__ lengths,
                           float* __restrict__ out_logits,
                           float* __restrict__ out_preds, int t)
{
    int b = blockIdx.x;
    __shared__ float sc[L_];
    int tid = threadIdx.x, lane = tid & 31, w = tid >> 5;
    int len = lengths[b];
    bool tvalid = (t < len);
    const float* qp = &g_pq[b*AP_];
    for (int l = w; l < L_; l += 8) {
        const float* kp = &g_ptr_keys[(b*L_+l)*AP_];
        float acc = 0.f;
#pragma unroll 4
        for (int a = lane; a < AP_; a += 32)
            acc += tanhf(qp[a] + kp[a]) * pv[a];
        for (int o=16;o;o>>=1) acc += __shfl_down_sync(0xffffffffu, acc, o);
        if (lane==0) {
            bool ok = tvalid && (l < len) && (g_fo[b*L_+l] >= t);
            float val = ok ? acc : NEGV;
            sc[l] = val;
            out_logits[(b*L_+t)*L_+l] = val;
        }
    }
    __syncthreads();
    if (w == 0 && out_preds) {
        float v0 = sc[lane], v1 = sc[lane+32];
        float bv; int bidx;
        if (v1 > v0) { bv = v1; bidx = lane+32; } else { bv = v0; bidx = lane; }
        for (int o=16;o;o>>=1) {
            float ov = __shfl_down_sync(0xffffffffu, bv, o);
            int   oi = __shfl_down_sync(0xffffffffu, bidx, o);
            if (ov > bv || (ov == bv && oi < bidx)) { bv = ov; bidx = oi; }
        }
        if (lane == 0) out_preds[b*L_+t] = (float)bidx;
    }
}

// ---------------- host ----------------
static float* symf(const void* sym) {
    void* p = nullptr;
    cudaGetSymbolAddress(&p, sym);
    return (float*)p;
}

extern "C" void kernel_launch(void* const* d_in, const int* in_sizes, int n_in,
                              void* d_out, int out_size)
{
    const float* inputs  = (const float*)d_in[0];
    const int*   lengths = (const int*)  d_in[1];
    const int*   targets = (const int*)  d_in[2];
    const float* W_in    = (const float*)d_in[3];
    const float* b_in    = (const float*)d_in[4];
    const float* enc_Wi  = (const float*)d_in[5];
    const float* enc_Wh  = (const float*)d_in[6];
    const float* enc_bi  = (const float*)d_in[7];
    const float* enc_bh  = (const float*)d_in[8];
    const float* dec_Wi  = (const float*)d_in[9];
    const float* dec_Wh  = (const float*)d_in[10];
    const float* dec_bi  = (const float*)d_in[11];
    const float* dec_bh  = (const float*)d_in[12];
    const float* s2s_Wq  = (const float*)d_in[13];
    const float* s2s_Wk  = (const float*)d_in[14];
    const float* s2s_v   = (const float*)d_in[15];
    const float* W_out   = (const float*)d_in[16];
    const float* b_out   = (const float*)d_in[17];
    const float* ptr_Wq  = (const float*)d_in[18];
    const float* ptr_Wk  = (const float*)d_in[19];
    const float* ptr_v   = (const float*)d_in[20];

    float* out = (float*)d_out;
    float* out_logits = out;
    float* out_preds  = (out_size >= B_*L_*L_ + B_*L_) ? (out + B_*L_*L_) : nullptr;

    float* p_dense    = symf(g_dense);
    float* p_encgi    = symf(g_enc_gi);
    float* p_decxgi   = symf(g_decx_gi);
    float* p_encout   = symf(g_enc_out);
    float* p_enckeys  = symf(g_enc_keys);
    float* p_ptrkeys  = symf(g_ptr_keys);
    float* p_h        = symf(g_h);
    float* p_gh       = symf(g_gh);
    float* p_q        = symf(g_q);
    float* p_dout     = symf(g_dout);
    float* p_pq       = symf(g_pq);

    // ---- one-time precompute ----
    zero_h_k<<<(B_*H_)/256, 256>>>();
    dense_in_k<<<(B_*L_*D_)/256, 256>>>(inputs, W_in, b_in);
    masks_k<<<B_, L_>>>(targets);
    // enc_gi = dense @ enc_Wi.T        [8192,1536] K=256
    sgemm_k<64,64,4,4,true><<<dim3(G3H_/64, (B_*L_)/64), 256>>>(
        p_dense, D_, enc_Wi, D_, nullptr, p_encgi, G3H_, D_);
    // decx_gi = dense @ dec_Wi[:,H:].T [8192,1536] K=256 (weights at column offset H, row stride 768)
    sgemm_k<64,64,4,4,true><<<dim3(G3H_/64, (B_*L_)/64), 256>>>(
        p_dense, D_, dec_Wi + H_, 768, nullptr, p_decxgi, G3H_, D_);
    // ptr_keys = dense @ ptr_Wk        [8192,256] K=256 (plain layout)
    sgemm_k<64,64,4,4,false><<<dim3(AP_/64, (B_*L_)/64), 256>>>(
        p_dense, D_, ptr_Wk, AP_, nullptr, p_ptrkeys, AP_, D_);

    // ---- encoder ----
    for (int t = 0; t < L_; t++) {
        sgemm_k<32,64,2,4,true><<<dim3(G3H_/64, B_/32), 256>>>(
            p_h, H_, enc_Wh, H_, nullptr, p_gh, G3H_, H_);
        enc_pointwise_k<<<(B_*H_)/256, 256>>>(enc_bi, enc_bh, lengths, t);
    }
    hidden0_k<<<(B_*H_)/256, 256>>>(lengths);
    // enc_keys = enc_out @ s2s_Wk      [8192,512] K=512 (plain layout)
    sgemm_k<64,64,4,4,false><<<dim3(AS_/64, (B_*L_)/64), 256>>>(
        p_encout, H_, s2s_Wk, AS_, nullptr, p_enckeys, AS_, H_);

    // ---- decoder ----
    for (int t = 0; t < L_; t++) {
        // q = h @ s2s_Wq  [128,512] K=512
        sgemm_k<32,64,2,4,false><<<dim3(AS_/64, B_/32), 256>>>(
            p_h, H_, s2s_Wq, AS_, nullptr, p_q, AS_, H_);
        attn_s2s_k<<<B_, 256>>>(s2s_v, lengths, t);
        dec_gates_k<<<dim3(G3H_/64, B_/32, 2), 256>>>(dec_Wh, dec_Wi);
        dec_pointwise_k<<<(B_*H_)/256, 256>>>(dec_bi, dec_bh, t);
        // dense_out = h @ W_out.T + b_out  [128,256] K=512
        sgemm_k<32,64,2,4,true><<<dim3(D_/64, B_/32), 256>>>(
            p_h, H_, W_out, H_, b_out, p_dout, D_, H_);
        // pq = dense_out @ ptr_Wq  [128,256] K=256
        sgemm_k<32,64,2,4,false><<<dim3(AP_/64, B_/32), 256>>>(
            p_dout, D_, ptr_Wq, AP_, nullptr, p_pq, AP_, D_);
        ptr_attn_k<<<B_, 256>>>(ptr_v, lengths, out_logits, out_preds, t);
    }
}